// round 7
// baseline (speedup 1.0000x reference)
#include <cuda_runtime.h>
#include <cstdint>

// ---------------- problem constants ----------------
#define V_    5000
#define F_    6144
#define PB_   (F_/2)          // 3072 pair-blocks per mesh
#define NMESH 4               // pred0, pred1, targ0, targ3

#define K625      (-901.68440055560213f)   // -625*log2(e)
#define SI_       (1803.3688011112043f)    // -2*K625
#define SN2       5.7707801635558536f      // 4*log2(e)
#define SN_       2.4022448509f            // sqrt(SN2)

#define TILE_J   256
#define NTB      (F_ / 256)                // 24 tiles of 256 (both i and j)

// work items: per sym combo, (ti, jb) with jb >= ti: 24+23+...+1 = 300
// cross combos: full 24x24 = 576
#define SYM_PER    300
#define N_SYMITEMS (4 * SYM_PER)           // 1200
#define CROSS_PER  (NTB * NTB)             // 576
#define N_ITEMS    (N_SYMITEMS + 2 * CROSS_PER)   // 2352

typedef unsigned long long ull;

// ---------------- device scratch ----------------
__device__ float g_fd[NMESH * PB_ * 16];
__device__ float g_L [NMESH * F_];
__device__ float g_bp[N_ITEMS * 3];

// ---------------- f32x2 helpers ----------------
__device__ __forceinline__ ull f2fma(ull a, ull b, ull c) {
    ull d; asm("fma.rn.f32x2 %0, %1, %2, %3;" : "=l"(d) : "l"(a), "l"(b), "l"(c)); return d;
}
__device__ __forceinline__ ull f2mul(ull a, ull b) {
    ull d; asm("mul.rn.f32x2 %0, %1, %2;" : "=l"(d) : "l"(a), "l"(b)); return d;
}
__device__ __forceinline__ ull f2add(ull a, ull b) {
    ull d; asm("add.rn.f32x2 %0, %1, %2;" : "=l"(d) : "l"(a), "l"(b)); return d;
}
__device__ __forceinline__ ull splat2(float x) {
    ull d; asm("mov.b64 %0, {%1, %1};" : "=l"(d) : "f"(x)); return d;
}
__device__ __forceinline__ ull pack2(float lo, float hi) {
    ull d; asm("mov.b64 %0, {%1, %2};" : "=l"(d) : "f"(lo), "f"(hi)); return d;
}
__device__ __forceinline__ ull ex2x2(ull a) {
    float lo, hi, rlo, rhi;
    asm("mov.b64 {%0, %1}, %2;" : "=f"(lo), "=f"(hi) : "l"(a));
    asm("ex2.approx.f32 %0, %1;" : "=f"(rlo) : "f"(lo));
    asm("ex2.approx.f32 %0, %1;" : "=f"(rhi) : "f"(hi));
    return pack2(rlo, rhi);
}
__device__ __forceinline__ float sum2(ull a) {
    float lo, hi;
    asm("mov.b64 {%0, %1}, %2;" : "=f"(lo), "=f"(hi) : "l"(a));
    return lo + hi;
}

// ---------------- kernel 1: per-face quantities ----------------
__global__ void mesh_kernel(const float* __restrict__ pred,
                            const float* __restrict__ targ,
                            const int*   __restrict__ faces) {
    int idx = blockIdx.x * blockDim.x + threadIdx.x;
    if (idx >= NMESH * F_) return;
    int m = idx / F_;
    int f = idx - m * F_;

    const float* Vb = (m < 2 ? pred : targ) + (m & 1) * (V_ * 3);

    int i0 = faces[3 * f + 0], i1 = faces[3 * f + 1], i2 = faces[3 * f + 2];
    float v0x = Vb[3*i0], v0y = Vb[3*i0+1], v0z = Vb[3*i0+2];
    float v1x = Vb[3*i1], v1y = Vb[3*i1+1], v1z = Vb[3*i1+2];
    float v2x = Vb[3*i2], v2y = Vb[3*i2+1], v2z = Vb[3*i2+2];

    const float third = 1.0f / 3.0f;
    float Cx = (v0x + v1x + v2x) * third;
    float Cy = (v0y + v1y + v2y) * third;
    float Cz = (v0z + v1z + v2z) * third;

    float e1x = v1x - v0x, e1y = v1y - v0y, e1z = v1z - v0z;
    float e2x = v2x - v0x, e2y = v2y - v0y, e2z = v2z - v0z;
    float Nx = 0.5f * (e1y * e2z - e1z * e2y);
    float Ny = 0.5f * (e1z * e2x - e1x * e2z);
    float Nz = 0.5f * (e1x * e2y - e1y * e2x);

    float n2 = Nx*Nx + Ny*Ny + Nz*Nz + 1e-24f;
    float L  = sqrtf(n2);
    float s  = SN_ / L;

    float A  = K625 * (Cx*Cx + Cy*Cy + Cz*Cz);
    float G  = log2f(L) - SN2;

    int base = m * (PB_ * 16) + (f >> 1) * 16 + (f & 1);
    g_fd[base + 0]  = Cx;
    g_fd[base + 2]  = Cy;
    g_fd[base + 4]  = Cz;
    g_fd[base + 6]  = A;
    g_fd[base + 8]  = Nx * s;
    g_fd[base + 10] = Ny * s;
    g_fd[base + 12] = Nz * s;
    g_fd[base + 14] = G;
    g_L[m * F_ + f] = L;
}

// ---------------- kernel 2: pairwise varifold products ----------------
// grid = 2352 equal work items (no null blocks). block = 256 threads, one
// i-face per thread (256-i tile), 256-j tile staged in 8 KB smem.
// Sym combos keep only jb >= ti; jb > ti weighted x2; jb == ti uses per-pair
// (j > i ? 2 : 0) weight plus the exact Li^2 diagonal.

template <bool DIAG>
__device__ __forceinline__ void tile_loop(const ulonglong2* __restrict__ s_tile,
                                          ull RX, ull RY, ull RZ, ull AiD,
                                          ull NX, ull NY, ull NZ,
                                          int jmi,           // jb*256 - i
                                          ull& A0, ull& A1, ull& A2) {
    ull a0 = A0, a1 = A1, a2 = A2;
    #pragma unroll 4
    for (int p = 0; p < TILE_J / 2; ++p) {
        ulonglong2 q0 = s_tile[p * 4 + 0];   // Cx | Cy
        ulonglong2 q1 = s_tile[p * 4 + 1];   // Cz | A
        ulonglong2 q2 = s_tile[p * 4 + 2];   // Nx | Ny
        ulonglong2 q3 = s_tile[p * 4 + 3];   // Nz | G

        ull arg = f2add(AiD, q1.y);
        arg = f2fma(RX, q0.x, arg);
        arg = f2fma(RY, q0.y, arg);
        arg = f2fma(RZ, q1.x, arg);

        ull narg = f2fma(NX, q2.x, q3.y);
        narg = f2fma(NY, q2.y, narg);
        narg = f2fma(NZ, q3.x, narg);

        ull y  = ex2x2(arg);     // exp(-625*d2)
        ull en = ex2x2(narg);    // Lj * exp(4*(ndot-1))

        if (DIAG) {
            float wlo = (2 * p + jmi     > 0) ? 2.0f : 0.0f;
            float whi = (2 * p + jmi + 1 > 0) ? 2.0f : 0.0f;
            en = f2mul(en, pack2(wlo, whi));
        }

        ull y2  = f2mul(y,  y);
        ull y4  = f2mul(y2, y2);
        ull y8  = f2mul(y4, y4);
        ull y16 = f2mul(y8, y8);
        ull y24 = f2mul(y16, y8);
        ull y25 = f2mul(y24, y);

        a0 = f2fma(en, y4,  a0);   // sigma = 0.02  (2500  = 4*625)
        a1 = f2fma(en, y16, a1);   // sigma = 0.01  (10000 = 16*625)
        a2 = f2fma(en, y25, a2);   // sigma = 0.008 (15625 = 25*625)
    }
    A0 = a0; A1 = a1; A2 = a2;
}

__global__ __launch_bounds__(256, 5)
void pair_kernel() {
    __shared__ ulonglong2 s_tile[(TILE_J / 2) * 4];   // 8 KB
    __shared__ float s_red[8][3];

    int bid = blockIdx.x;
    int tid = threadIdx.x;

    // ---- decode work item ----
    int mi, mj, ti, jb;
    bool diag = false;
    float mult = 1.0f;
    if (bid < N_SYMITEMS) {
        int c = bid / SYM_PER;
        int k = bid - c * SYM_PER;
        int row = 0;
        while (k >= NTB - row) { k -= NTB - row; ++row; }   // triangular decode
        ti = row; jb = row + k;
        mi = mj = c;
        diag = (jb == ti);
        mult = diag ? 1.0f : 2.0f;
    } else {
        int k = bid - N_SYMITEMS;
        int c = k / CROSS_PER; k -= c * CROSS_PER;
        ti = k / NTB; jb = k - ti * NTB;
        mi = c; mj = c + 2;
    }

    int i = ti * 256 + tid;

    int ibase = mi * (PB_ * 16) + (i >> 1) * 16 + (i & 1);
    ull RX  = splat2(SI_ * g_fd[ibase + 0]);
    ull RY  = splat2(SI_ * g_fd[ibase + 2]);
    ull RZ  = splat2(SI_ * g_fd[ibase + 4]);
    ull AiD = splat2(g_fd[ibase + 6]);
    ull NX  = splat2(g_fd[ibase + 8]);
    ull NY  = splat2(g_fd[ibase + 10]);
    ull NZ  = splat2(g_fd[ibase + 12]);
    float Li = g_L[mi * F_ + i];

    // stage the 256-face j-tile (128 pair-blocks * 64 B = 8 KB)
    {
        float4* dst = (float4*)s_tile;
        const float4* src = (const float4*)(g_fd + (size_t)mj * (PB_ * 16))
                          + (size_t)jb * (TILE_J / 2) * 4;
        #pragma unroll
        for (int k = 0; k < (TILE_J / 2) * 4 / 256; ++k)
            dst[tid + k * 256] = src[tid + k * 256];
    }
    __syncthreads();

    ull A0 = splat2(0.f), A1 = splat2(0.f), A2 = splat2(0.f);
    if (diag)
        tile_loop<true >(s_tile, RX, RY, RZ, AiD, NX, NY, NZ, jb * 256 - i, A0, A1, A2);
    else
        tile_loop<false>(s_tile, RX, RY, RZ, AiD, NX, NY, NZ, 0, A0, A1, A2);

    float r0 = mult * Li * sum2(A0);
    float r1 = mult * Li * sum2(A1);
    float r2 = mult * Li * sum2(A2);
    if (diag) {                              // K(i,i) = 1 exactly
        float d = Li * Li;
        r0 += d; r1 += d; r2 += d;
    }

    #pragma unroll
    for (int o = 16; o > 0; o >>= 1) {
        r0 += __shfl_down_sync(0xffffffffu, r0, o);
        r1 += __shfl_down_sync(0xffffffffu, r1, o);
        r2 += __shfl_down_sync(0xffffffffu, r2, o);
    }
    int wid = tid >> 5, lane = tid & 31;
    if (lane == 0) { s_red[wid][0] = r0; s_red[wid][1] = r1; s_red[wid][2] = r2; }
    __syncthreads();
    if (tid == 0) {
        float s0 = 0.f, s1 = 0.f, s2 = 0.f;
        #pragma unroll
        for (int w = 0; w < 8; ++w) { s0 += s_red[w][0]; s1 += s_red[w][1]; s2 += s_red[w][2]; }
        g_bp[bid * 3 + 0] = s0; g_bp[bid * 3 + 1] = s1; g_bp[bid * 3 + 2] = s2;
    }
}

// ---------------- kernel 3: final combine ----------------
// 18 warps: one per (combo, sigma); lanes stride over that combo's items.
__global__ void combine_kernel(float* __restrict__ out) {
    __shared__ float sB[18];
    int t = threadIdx.x;           // 576 threads
    int cs = t >> 5, lane = t & 31;
    int cmb = cs / 3, s = cs - cmb * 3;

    int lo, n;
    if (cmb < 4) { lo = cmb * SYM_PER;                     n = SYM_PER;   }
    else         { lo = N_SYMITEMS + (cmb - 4) * CROSS_PER; n = CROSS_PER; }

    float acc = 0.f;
    for (int k = lane; k < n; k += 32)
        acc += g_bp[(lo + k) * 3 + s];
    #pragma unroll
    for (int o = 16; o > 0; o >>= 1)
        acc += __shfl_down_sync(0xffffffffu, acc, o);
    if (lane == 0) sB[cs] = acc;
    __syncthreads();

    if (t == 0) {
        const float w[3] = {1.0f, 0.25f, 0.16f};
        float loss = 0.f;
        #pragma unroll
        for (int b = 0; b < 2; ++b)
            #pragma unroll
            for (int s2 = 0; s2 < 3; ++s2)
                loss += w[s2] * (sB[b * 3 + s2]             // pss  (mesh b)
                                 - 2.0f * sB[(4 + b) * 3 + s2]   // pst
                                 + sB[(2 + b) * 3 + s2]);        // ptt
        out[0] = 0.5f * loss;   // mean over B=2
    }
}

// ncu's fixed capture lands on global launch index 3 (verified R1-R6).
// Fillers occupy indices 1 and 2 so index 3 = pair_kernel.
__global__ void filler1_kernel() {}
__global__ void filler2_kernel() {}

// ---------------- launch ----------------
extern "C" void kernel_launch(void* const* d_in, const int* in_sizes, int n_in,
                              void* d_out, int out_size) {
    const float* pred  = (const float*)d_in[0];
    const float* targ  = (const float*)d_in[1];
    const int*   faces = (const int*)d_in[2];
    float* out = (float*)d_out;

    mesh_kernel<<<(NMESH * F_ + 255) / 256, 256>>>(pred, targ, faces);   // idx 0
    filler1_kernel<<<1, 32>>>();                                         // idx 1
    filler2_kernel<<<1, 32>>>();                                         // idx 2
    pair_kernel<<<N_ITEMS, 256>>>();                                     // idx 3
    combine_kernel<<<1, 576>>>(out);                                     // idx 4
}

// round 9
// speedup vs baseline: 1.0549x; 1.0549x over previous
#include <cuda_runtime.h>
#include <cstdint>

// ---------------- problem constants ----------------
#define V_    5000
#define F_    6144
#define PB_   (F_/2)          // 3072 pair-blocks per mesh
#define NMESH 4               // pred0, pred1, targ0, targ1

#define K625      (-901.68440055560213f)   // -625*log2(e)
#define SI_       (1803.3688011112043f)    // -2*K625
#define SN2       5.7707801635558536f      // 4*log2(e)
#define SN_       2.4022448509f            // sqrt(SN2)

#define TILE_J   256
#define NTBJ     (F_ / TILE_J)             // 24 j-tiles of 256
#define ITILE    512
#define NTBI     (F_ / ITILE)              // 12 i-tiles of 512 (2 i per thread)

// sym combo items: (ti, jb) with jb >= 2*ti : sum_{ti=0..11} (24-2ti) = 156
#define SYM_PER    156
#define N_SYMITEMS (4 * SYM_PER)           // 624
#define CROSS_PER  (NTBI * NTBJ)           // 288
#define N_ITEMS    (N_SYMITEMS + 2 * CROSS_PER)   // 1200

typedef unsigned long long ull;

// ---------------- device scratch ----------------
__device__ float g_fd[NMESH * PB_ * 16];
__device__ float g_L [NMESH * F_];
__device__ float g_bp[N_ITEMS * 3];

// ---------------- f32x2 helpers ----------------
__device__ __forceinline__ ull f2fma(ull a, ull b, ull c) {
    ull d; asm("fma.rn.f32x2 %0, %1, %2, %3;" : "=l"(d) : "l"(a), "l"(b), "l"(c)); return d;
}
__device__ __forceinline__ ull f2mul(ull a, ull b) {
    ull d; asm("mul.rn.f32x2 %0, %1, %2;" : "=l"(d) : "l"(a), "l"(b)); return d;
}
__device__ __forceinline__ ull f2add(ull a, ull b) {
    ull d; asm("add.rn.f32x2 %0, %1, %2;" : "=l"(d) : "l"(a), "l"(b)); return d;
}
__device__ __forceinline__ ull splat2(float x) {
    ull d; asm("mov.b64 %0, {%1, %1};" : "=l"(d) : "f"(x)); return d;
}
__device__ __forceinline__ ull pack2(float lo, float hi) {
    ull d; asm("mov.b64 %0, {%1, %2};" : "=l"(d) : "f"(lo), "f"(hi)); return d;
}
__device__ __forceinline__ ull ex2x2(ull a) {
    float lo, hi, rlo, rhi;
    asm("mov.b64 {%0, %1}, %2;" : "=f"(lo), "=f"(hi) : "l"(a));
    asm("ex2.approx.f32 %0, %1;" : "=f"(rlo) : "f"(lo));
    asm("ex2.approx.f32 %0, %1;" : "=f"(rhi) : "f"(hi));
    return pack2(rlo, rhi);
}
__device__ __forceinline__ float sum2(ull a) {
    float lo, hi;
    asm("mov.b64 {%0, %1}, %2;" : "=f"(lo), "=f"(hi) : "l"(a));
    return lo + hi;
}

// ---------------- kernel 1: per-face quantities ----------------
__global__ void mesh_kernel(const float* __restrict__ pred,
                            const float* __restrict__ targ,
                            const int*   __restrict__ faces) {
    int idx = blockIdx.x * blockDim.x + threadIdx.x;
    if (idx >= NMESH * F_) return;
    int m = idx / F_;
    int f = idx - m * F_;

    const float* Vb = (m < 2 ? pred : targ) + (m & 1) * (V_ * 3);

    int i0 = faces[3 * f + 0], i1 = faces[3 * f + 1], i2 = faces[3 * f + 2];
    float v0x = Vb[3*i0], v0y = Vb[3*i0+1], v0z = Vb[3*i0+2];
    float v1x = Vb[3*i1], v1y = Vb[3*i1+1], v1z = Vb[3*i1+2];
    float v2x = Vb[3*i2], v2y = Vb[3*i2+1], v2z = Vb[3*i2+2];

    const float third = 1.0f / 3.0f;
    float Cx = (v0x + v1x + v2x) * third;
    float Cy = (v0y + v1y + v2y) * third;
    float Cz = (v0z + v1z + v2z) * third;

    float e1x = v1x - v0x, e1y = v1y - v0y, e1z = v1z - v0z;
    float e2x = v2x - v0x, e2y = v2y - v0y, e2z = v2z - v0z;
    float Nx = 0.5f * (e1y * e2z - e1z * e2y);
    float Ny = 0.5f * (e1z * e2x - e1x * e2z);
    float Nz = 0.5f * (e1x * e2y - e1y * e2x);

    float n2 = Nx*Nx + Ny*Ny + Nz*Nz + 1e-24f;
    float L  = sqrtf(n2);
    float s  = SN_ / L;

    float A  = K625 * (Cx*Cx + Cy*Cy + Cz*Cz);
    float G  = log2f(L) - SN2;

    int base = m * (PB_ * 16) + (f >> 1) * 16 + (f & 1);
    g_fd[base + 0]  = Cx;
    g_fd[base + 2]  = Cy;
    g_fd[base + 4]  = Cz;
    g_fd[base + 6]  = A;
    g_fd[base + 8]  = Nx * s;
    g_fd[base + 10] = Ny * s;
    g_fd[base + 12] = Nz * s;
    g_fd[base + 14] = G;
    g_L[m * F_ + f] = L;
}

// ---------------- kernel 2: pairwise varifold products ----------------
// grid = 1200 equal work items. block = 256 threads; each thread owns TWO
// i-faces (i, i+256) of a 512-i tile; one 256-j tile staged in 8 KB smem.
// Sym combos keep j-tiles with jb >= 2*ti; tiles fully above the diagonal
// get x2; the two straddling tiles (jb>>1 == ti) use per-pair weights plus
// the exact Li^2 diagonal.

struct IFace { ull RX, RY, RZ, AiD, NX, NY, NZ; };
struct Acc3  { ull a0, a1, a2; };

template <bool DIAG>
__device__ __forceinline__ void tile_loop2(const ulonglong2* __restrict__ s_tile,
                                           const IFace& I0, const IFace& I1,
                                           int jmi0, int jmi1,
                                           Acc3& A0, Acc3& A1) {
    ull a00 = A0.a0, a01 = A0.a1, a02 = A0.a2;
    ull a10 = A1.a0, a11 = A1.a1, a12 = A1.a2;
    #pragma unroll 4
    for (int p = 0; p < TILE_J / 2; ++p) {
        ulonglong2 q0 = s_tile[p * 4 + 0];   // Cx | Cy
        ulonglong2 q1 = s_tile[p * 4 + 1];   // Cz | A
        ulonglong2 q2 = s_tile[p * 4 + 2];   // Nx | Ny
        ulonglong2 q3 = s_tile[p * 4 + 3];   // Nz | G

        // -------- chain 0: exponents --------
        ull arg0 = f2add(I0.AiD, q1.y);
        arg0 = f2fma(I0.RX, q0.x, arg0);
        arg0 = f2fma(I0.RY, q0.y, arg0);
        arg0 = f2fma(I0.RZ, q1.x, arg0);
        ull narg0 = f2fma(I0.NX, q2.x, q3.y);
        narg0 = f2fma(I0.NY, q2.y, narg0);
        narg0 = f2fma(I0.NZ, q3.x, narg0);

        // -------- chain 1: exponents --------
        ull arg1 = f2add(I1.AiD, q1.y);
        arg1 = f2fma(I1.RX, q0.x, arg1);
        arg1 = f2fma(I1.RY, q0.y, arg1);
        arg1 = f2fma(I1.RZ, q1.x, arg1);
        ull narg1 = f2fma(I1.NX, q2.x, q3.y);
        narg1 = f2fma(I1.NY, q2.y, narg1);
        narg1 = f2fma(I1.NZ, q3.x, narg1);

        ull y0  = ex2x2(arg0);
        ull en0 = ex2x2(narg0);
        ull y1  = ex2x2(arg1);
        ull en1 = ex2x2(narg1);

        if (DIAG) {
            float w0lo = (2 * p + jmi0     > 0) ? 2.0f : 0.0f;
            float w0hi = (2 * p + jmi0 + 1 > 0) ? 2.0f : 0.0f;
            en0 = f2mul(en0, pack2(w0lo, w0hi));
            float w1lo = (2 * p + jmi1     > 0) ? 2.0f : 0.0f;
            float w1hi = (2 * p + jmi1 + 1 > 0) ? 2.0f : 0.0f;
            en1 = f2mul(en1, pack2(w1lo, w1hi));
        }

        // -------- powers + accum, chain 0 (addition chain 1,2,4,8,16,24,25)
        {
            ull y2  = f2mul(y0, y0);
            ull y4  = f2mul(y2, y2);
            ull y8  = f2mul(y4, y4);
            ull y16 = f2mul(y8, y8);
            ull y24 = f2mul(y16, y8);
            ull y25 = f2mul(y24, y0);
            a00 = f2fma(en0, y4,  a00);   // sigma=0.02  (2500 =4*625)
            a01 = f2fma(en0, y16, a01);   // sigma=0.01  (10000=16*625)
            a02 = f2fma(en0, y25, a02);   // sigma=0.008 (15625=25*625)
        }
        // -------- powers + accum, chain 1 --------
        {
            ull y2  = f2mul(y1, y1);
            ull y4  = f2mul(y2, y2);
            ull y8  = f2mul(y4, y4);
            ull y16 = f2mul(y8, y8);
            ull y24 = f2mul(y16, y8);
            ull y25 = f2mul(y24, y1);
            a10 = f2fma(en1, y4,  a10);
            a11 = f2fma(en1, y16, a11);
            a12 = f2fma(en1, y25, a12);
        }
    }
    A0.a0 = a00; A0.a1 = a01; A0.a2 = a02;
    A1.a0 = a10; A1.a1 = a11; A1.a2 = a12;
}

__device__ __forceinline__ void load_iface(int m, int i, IFace& I) {
    int b = m * (PB_ * 16) + (i >> 1) * 16 + (i & 1);
    I.RX  = splat2(SI_ * g_fd[b + 0]);
    I.RY  = splat2(SI_ * g_fd[b + 2]);
    I.RZ  = splat2(SI_ * g_fd[b + 4]);
    I.AiD = splat2(g_fd[b + 6]);
    I.NX  = splat2(g_fd[b + 8]);
    I.NY  = splat2(g_fd[b + 10]);
    I.NZ  = splat2(g_fd[b + 12]);
}

__global__ __launch_bounds__(256, 3)
void pair_kernel() {
    __shared__ ulonglong2 s_tile[(TILE_J / 2) * 4];   // 8 KB
    __shared__ float s_red[8][3];

    int bid = blockIdx.x;
    int tid = threadIdx.x;

    // ---- decode work item ----
    int mi, mj, ti, jb;
    bool diag = false;
    float mult = 1.0f;
    if (bid < N_SYMITEMS) {
        int c = bid / SYM_PER;
        int k = bid - c * SYM_PER;
        int row = 0;
        while (k >= NTBJ - 2 * row) { k -= NTBJ - 2 * row; ++row; }
        ti = row; jb = 2 * row + k;
        mi = mj = c;
        diag = ((jb >> 1) == ti);
        mult = diag ? 1.0f : 2.0f;
    } else {
        int k = bid - N_SYMITEMS;
        int c = k / CROSS_PER; k -= c * CROSS_PER;
        ti = k / NTBJ; jb = k - ti * NTBJ;
        mi = c; mj = c + 2;
    }

    int i0 = ti * ITILE + tid;
    int i1 = i0 + 256;

    IFace I0, I1;
    load_iface(mi, i0, I0);
    load_iface(mi, i1, I1);
    float Li0 = g_L[mi * F_ + i0];
    float Li1 = g_L[mi * F_ + i1];

    // stage the 256-face j-tile (128 pair-blocks * 64 B = 8 KB)
    {
        float4* dst = (float4*)s_tile;
        const float4* src = (const float4*)(g_fd + (size_t)mj * (PB_ * 16))
                          + (size_t)jb * (TILE_J / 2) * 4;
        #pragma unroll
        for (int k = 0; k < (TILE_J / 2) * 4 / 256; ++k)
            dst[tid + k * 256] = src[tid + k * 256];
    }
    __syncthreads();

    Acc3 A0, A1;
    A0.a0 = splat2(0.f); A0.a1 = splat2(0.f); A0.a2 = splat2(0.f);
    A1.a0 = splat2(0.f); A1.a1 = splat2(0.f); A1.a2 = splat2(0.f);

    if (diag)
        tile_loop2<true >(s_tile, I0, I1, jb * TILE_J - i0, jb * TILE_J - i1, A0, A1);
    else
        tile_loop2<false>(s_tile, I0, I1, 0, 0, A0, A1);

    float r0 = mult * (Li0 * sum2(A0.a0) + Li1 * sum2(A1.a0));
    float r1 = mult * (Li0 * sum2(A0.a1) + Li1 * sum2(A1.a1));
    float r2 = mult * (Li0 * sum2(A0.a2) + Li1 * sum2(A1.a2));
    if (diag) {                              // K(i,i) = 1 exactly
        float d = 0.f;
        if ((i0 >> 8) == jb) d += Li0 * Li0;
        if ((i1 >> 8) == jb) d += Li1 * Li1;
        r0 += d; r1 += d; r2 += d;
    }

    #pragma unroll
    for (int o = 16; o > 0; o >>= 1) {
        r0 += __shfl_down_sync(0xffffffffu, r0, o);
        r1 += __shfl_down_sync(0xffffffffu, r1, o);
        r2 += __shfl_down_sync(0xffffffffu, r2, o);
    }
    int wid = tid >> 5, lane = tid & 31;
    if (lane == 0) { s_red[wid][0] = r0; s_red[wid][1] = r1; s_red[wid][2] = r2; }
    __syncthreads();
    if (tid == 0) {
        float s0 = 0.f, s1 = 0.f, s2 = 0.f;
        #pragma unroll
        for (int w = 0; w < 8; ++w) { s0 += s_red[w][0]; s1 += s_red[w][1]; s2 += s_red[w][2]; }
        g_bp[bid * 3 + 0] = s0; g_bp[bid * 3 + 1] = s1; g_bp[bid * 3 + 2] = s2;
    }
}

// ---------------- kernel 3: final combine ----------------
// 18 warps: one per (combo, sigma); lanes stride over that combo's items.
// combos 0..3 = sym meshes (pred0, pred1, targ0, targ1); 4..5 = cross (b=0,1).
__global__ void combine_kernel(float* __restrict__ out) {
    __shared__ float sB[18];
    int t = threadIdx.x;           // 576 threads
    int cs = t >> 5, lane = t & 31;
    int cmb = cs / 3, s = cs - cmb * 3;

    int lo, n;
    if (cmb < 4) { lo = cmb * SYM_PER;                      n = SYM_PER;   }
    else         { lo = N_SYMITEMS + (cmb - 4) * CROSS_PER; n = CROSS_PER; }

    float acc = 0.f;
    for (int k = lane; k < n; k += 32)
        acc += g_bp[(lo + k) * 3 + s];
    #pragma unroll
    for (int o = 16; o > 0; o >>= 1)
        acc += __shfl_down_sync(0xffffffffu, acc, o);
    if (lane == 0) sB[cs] = acc;
    __syncthreads();

    if (t == 0) {
        const float w[3] = {1.0f, 0.25f, 0.16f};
        float loss = 0.f;
        #pragma unroll
        for (int b = 0; b < 2; ++b)
            #pragma unroll
            for (int s2 = 0; s2 < 3; ++s2)
                loss += w[s2] * (sB[b * 3 + s2]                  // pss
                                 - 2.0f * sB[(4 + b) * 3 + s2]   // pst
                                 + sB[(2 + b) * 3 + s2]);        // ptt
        out[0] = 0.5f * loss;   // mean over B=2
    }
}

// ncu's fixed capture lands on global launch index 3 (verified R1-R7).
// Fillers occupy indices 1 and 2 so index 3 = pair_kernel.
__global__ void filler1_kernel() {}
__global__ void filler2_kernel() {}

// ---------------- launch ----------------
extern "C" void kernel_launch(void* const* d_in, const int* in_sizes, int n_in,
                              void* d_out, int out_size) {
    const float* pred  = (const float*)d_in[0];
    const float* targ  = (const float*)d_in[1];
    const int*   faces = (const int*)d_in[2];
    float* out = (float*)d_out;

    mesh_kernel<<<(NMESH * F_ + 255) / 256, 256>>>(pred, targ, faces);   // idx 0
    filler1_kernel<<<1, 32>>>();                                         // idx 1
    filler2_kernel<<<1, 32>>>();                                         // idx 2
    pair_kernel<<<N_ITEMS, 256>>>();                                     // idx 3
    combine_kernel<<<1, 576>>>(out);                                     // idx 4
}

// round 10
// speedup vs baseline: 1.0633x; 1.0079x over previous
#include <cuda_runtime.h>
#include <cstdint>

// ---------------- problem constants ----------------
#define V_    5000
#define F_    6144
#define PB_   (F_/2)          // 3072 pair-blocks per mesh
#define NMESH 4               // pred0, pred1, targ0, targ1

#define K625      (-901.68440055560213f)   // -625*log2(e)
#define SI_       (1803.3688011112043f)    // -2*K625
#define SN2       5.7707801635558536f      // 4*log2(e)
#define SN_       2.4022448509f            // sqrt(SN2)

#define TILE_J   256
#define NTBJ     (F_ / TILE_J)             // 24 j-tiles of 256
#define ITILE    512
#define NTBI     (F_ / ITILE)              // 12 i-tiles of 512 (2 i per thread)

// sym combo items: (ti, jb) with jb >= 2*ti : sum_{ti=0..11} (24-2ti) = 156
#define SYM_PER    156
#define N_SYMITEMS (4 * SYM_PER)           // 624
#define CROSS_PER  (NTBI * NTBJ)           // 288
#define N_ITEMS    (N_SYMITEMS + 2 * CROSS_PER)   // 1200

typedef unsigned long long ull;

// ---------------- device scratch ----------------
__device__ float g_fd[NMESH * PB_ * 16];
__device__ float g_L [NMESH * F_];
__device__ float g_bp[N_ITEMS * 3];

// ---------------- f32x2 helpers ----------------
__device__ __forceinline__ ull f2fma(ull a, ull b, ull c) {
    ull d; asm("fma.rn.f32x2 %0, %1, %2, %3;" : "=l"(d) : "l"(a), "l"(b), "l"(c)); return d;
}
__device__ __forceinline__ ull f2mul(ull a, ull b) {
    ull d; asm("mul.rn.f32x2 %0, %1, %2;" : "=l"(d) : "l"(a), "l"(b)); return d;
}
__device__ __forceinline__ ull f2add(ull a, ull b) {
    ull d; asm("add.rn.f32x2 %0, %1, %2;" : "=l"(d) : "l"(a), "l"(b)); return d;
}
__device__ __forceinline__ ull splat2(float x) {
    ull d; asm("mov.b64 %0, {%1, %1};" : "=l"(d) : "f"(x)); return d;
}
__device__ __forceinline__ ull pack2(float lo, float hi) {
    ull d; asm("mov.b64 %0, {%1, %2};" : "=l"(d) : "f"(lo), "f"(hi)); return d;
}
__device__ __forceinline__ ull ex2x2(ull a) {
    ull r;
    asm("{\n\t"
        ".reg .f32 lo, hi;\n\t"
        "mov.b64 {lo, hi}, %1;\n\t"
        "ex2.approx.f32 lo, lo;\n\t"
        "ex2.approx.f32 hi, hi;\n\t"
        "mov.b64 %0, {lo, hi};\n\t"
        "}" : "=l"(r) : "l"(a));
    return r;
}
__device__ __forceinline__ float sum2(ull a) {
    float lo, hi;
    asm("mov.b64 {%0, %1}, %2;" : "=f"(lo), "=f"(hi) : "l"(a));
    return lo + hi;
}

// ---------------- kernel 1: per-face quantities ----------------
__global__ void mesh_kernel(const float* __restrict__ pred,
                            const float* __restrict__ targ,
                            const int*   __restrict__ faces) {
    int idx = blockIdx.x * blockDim.x + threadIdx.x;
    if (idx >= NMESH * F_) return;
    int m = idx / F_;
    int f = idx - m * F_;

    const float* Vb = (m < 2 ? pred : targ) + (m & 1) * (V_ * 3);

    int i0 = faces[3 * f + 0], i1 = faces[3 * f + 1], i2 = faces[3 * f + 2];
    float v0x = Vb[3*i0], v0y = Vb[3*i0+1], v0z = Vb[3*i0+2];
    float v1x = Vb[3*i1], v1y = Vb[3*i1+1], v1z = Vb[3*i1+2];
    float v2x = Vb[3*i2], v2y = Vb[3*i2+1], v2z = Vb[3*i2+2];

    const float third = 1.0f / 3.0f;
    float Cx = (v0x + v1x + v2x) * third;
    float Cy = (v0y + v1y + v2y) * third;
    float Cz = (v0z + v1z + v2z) * third;

    float e1x = v1x - v0x, e1y = v1y - v0y, e1z = v1z - v0z;
    float e2x = v2x - v0x, e2y = v2y - v0y, e2z = v2z - v0z;
    float Nx = 0.5f * (e1y * e2z - e1z * e2y);
    float Ny = 0.5f * (e1z * e2x - e1x * e2z);
    float Nz = 0.5f * (e1x * e2y - e1y * e2x);

    float n2 = Nx*Nx + Ny*Ny + Nz*Nz + 1e-24f;
    float L  = sqrtf(n2);
    float s  = SN_ / L;

    float A  = K625 * (Cx*Cx + Cy*Cy + Cz*Cz);
    float G  = log2f(L) - SN2;

    int base = m * (PB_ * 16) + (f >> 1) * 16 + (f & 1);
    g_fd[base + 0]  = Cx;
    g_fd[base + 2]  = Cy;
    g_fd[base + 4]  = Cz;
    g_fd[base + 6]  = A;
    g_fd[base + 8]  = Nx * s;
    g_fd[base + 10] = Ny * s;
    g_fd[base + 12] = Nz * s;
    g_fd[base + 14] = G;
    g_L[m * F_ + f] = L;
}

// ---------------- kernel 2: pairwise varifold products ----------------
// grid = 1200 equal work items. block = 256 threads; each thread owns TWO
// i-faces (i, i+256) of a 512-i tile; one 256-j tile staged in 8 KB smem.

struct IFace { ull RX, RY, RZ, AiD, NX, NY, NZ; };
struct Acc3  { ull a0, a1, a2; };

template <bool DIAG>
__device__ __forceinline__ void tile_loop2(const ulonglong2* __restrict__ s_tile,
                                           const IFace& I0, const IFace& I1,
                                           int jmi0, int jmi1,
                                           Acc3& A0, Acc3& A1) {
    ull a00 = A0.a0, a01 = A0.a1, a02 = A0.a2;
    ull a10 = A1.a0, a11 = A1.a1, a12 = A1.a2;
    #pragma unroll 8
    for (int p = 0; p < TILE_J / 2; ++p) {
        ulonglong2 q0 = s_tile[p * 4 + 0];   // Cx | Cy
        ulonglong2 q1 = s_tile[p * 4 + 1];   // Cz | A
        ulonglong2 q2 = s_tile[p * 4 + 2];   // Nx | Ny
        ulonglong2 q3 = s_tile[p * 4 + 3];   // Nz | G

        // -------- chain 0: exponents (two-partial trees, depth 3) --------
        ull p0a = f2fma(I0.RX, q0.x, I0.AiD);
        ull p0b = f2fma(I0.RY, q0.y, q1.y);
        p0a = f2fma(I0.RZ, q1.x, p0a);
        ull arg0 = f2add(p0a, p0b);
        ull n0a = f2fma(I0.NX, q2.x, q3.y);
        ull n0b = f2mul(I0.NY, q2.y);
        n0a = f2fma(I0.NZ, q3.x, n0a);
        ull narg0 = f2add(n0a, n0b);

        // -------- chain 1: exponents --------
        ull p1a = f2fma(I1.RX, q0.x, I1.AiD);
        ull p1b = f2fma(I1.RY, q0.y, q1.y);
        p1a = f2fma(I1.RZ, q1.x, p1a);
        ull arg1 = f2add(p1a, p1b);
        ull n1a = f2fma(I1.NX, q2.x, q3.y);
        ull n1b = f2mul(I1.NY, q2.y);
        n1a = f2fma(I1.NZ, q3.x, n1a);
        ull narg1 = f2add(n1a, n1b);

        ull y0  = ex2x2(arg0);
        ull en0 = ex2x2(narg0);
        ull y1  = ex2x2(arg1);
        ull en1 = ex2x2(narg1);

        if (DIAG) {
            float w0lo = (2 * p + jmi0     > 0) ? 2.0f : 0.0f;
            float w0hi = (2 * p + jmi0 + 1 > 0) ? 2.0f : 0.0f;
            en0 = f2mul(en0, pack2(w0lo, w0hi));
            float w1lo = (2 * p + jmi1     > 0) ? 2.0f : 0.0f;
            float w1hi = (2 * p + jmi1 + 1 > 0) ? 2.0f : 0.0f;
            en1 = f2mul(en1, pack2(w1lo, w1hi));
        }

        // -------- powers + accum, chain 0 (depth-5: y9 || y16) --------
        {
            ull y2  = f2mul(y0, y0);
            ull y4  = f2mul(y2, y2);
            ull y8  = f2mul(y4, y4);
            ull y9  = f2mul(y8, y0);
            ull y16 = f2mul(y8, y8);
            ull y25 = f2mul(y16, y9);
            a00 = f2fma(en0, y4,  a00);   // sigma=0.02  (2500 =4*625)
            a01 = f2fma(en0, y16, a01);   // sigma=0.01  (10000=16*625)
            a02 = f2fma(en0, y25, a02);   // sigma=0.008 (15625=25*625)
        }
        // -------- powers + accum, chain 1 --------
        {
            ull y2  = f2mul(y1, y1);
            ull y4  = f2mul(y2, y2);
            ull y8  = f2mul(y4, y4);
            ull y9  = f2mul(y8, y1);
            ull y16 = f2mul(y8, y8);
            ull y25 = f2mul(y16, y9);
            a10 = f2fma(en1, y4,  a10);
            a11 = f2fma(en1, y16, a11);
            a12 = f2fma(en1, y25, a12);
        }
    }
    A0.a0 = a00; A0.a1 = a01; A0.a2 = a02;
    A1.a0 = a10; A1.a1 = a11; A1.a2 = a12;
}

__device__ __forceinline__ void load_iface(int m, int i, IFace& I) {
    int b = m * (PB_ * 16) + (i >> 1) * 16 + (i & 1);
    I.RX  = splat2(SI_ * g_fd[b + 0]);
    I.RY  = splat2(SI_ * g_fd[b + 2]);
    I.RZ  = splat2(SI_ * g_fd[b + 4]);
    I.AiD = splat2(g_fd[b + 6]);
    I.NX  = splat2(g_fd[b + 8]);
    I.NY  = splat2(g_fd[b + 10]);
    I.NZ  = splat2(g_fd[b + 12]);
}

__global__ __launch_bounds__(256, 3)
void pair_kernel() {
    __shared__ ulonglong2 s_tile[(TILE_J / 2) * 4];   // 8 KB
    __shared__ float s_red[8][3];

    int bid = blockIdx.x;
    int tid = threadIdx.x;

    // ---- decode work item ----
    int mi, mj, ti, jb;
    bool diag = false;
    float mult = 1.0f;
    if (bid < N_SYMITEMS) {
        int c = bid / SYM_PER;
        int k = bid - c * SYM_PER;
        int row = 0;
        while (k >= NTBJ - 2 * row) { k -= NTBJ - 2 * row; ++row; }
        ti = row; jb = 2 * row + k;
        mi = mj = c;
        diag = ((jb >> 1) == ti);
        mult = diag ? 1.0f : 2.0f;
    } else {
        int k = bid - N_SYMITEMS;
        int c = k / CROSS_PER; k -= c * CROSS_PER;
        ti = k / NTBJ; jb = k - ti * NTBJ;
        mi = c; mj = c + 2;
    }

    int i0 = ti * ITILE + tid;
    int i1 = i0 + 256;

    IFace I0, I1;
    load_iface(mi, i0, I0);
    load_iface(mi, i1, I1);
    float Li0 = g_L[mi * F_ + i0];
    float Li1 = g_L[mi * F_ + i1];

    // stage the 256-face j-tile (128 pair-blocks * 64 B = 8 KB)
    {
        float4* dst = (float4*)s_tile;
        const float4* src = (const float4*)(g_fd + (size_t)mj * (PB_ * 16))
                          + (size_t)jb * (TILE_J / 2) * 4;
        #pragma unroll
        for (int k = 0; k < (TILE_J / 2) * 4 / 256; ++k)
            dst[tid + k * 256] = src[tid + k * 256];
    }
    __syncthreads();

    Acc3 A0, A1;
    A0.a0 = splat2(0.f); A0.a1 = splat2(0.f); A0.a2 = splat2(0.f);
    A1.a0 = splat2(0.f); A1.a1 = splat2(0.f); A1.a2 = splat2(0.f);

    if (diag)
        tile_loop2<true >(s_tile, I0, I1, jb * TILE_J - i0, jb * TILE_J - i1, A0, A1);
    else
        tile_loop2<false>(s_tile, I0, I1, 0, 0, A0, A1);

    float r0 = mult * (Li0 * sum2(A0.a0) + Li1 * sum2(A1.a0));
    float r1 = mult * (Li0 * sum2(A0.a1) + Li1 * sum2(A1.a1));
    float r2 = mult * (Li0 * sum2(A0.a2) + Li1 * sum2(A1.a2));
    if (diag) {                              // K(i,i) = 1 exactly
        float d = 0.f;
        if ((i0 >> 8) == jb) d += Li0 * Li0;
        if ((i1 >> 8) == jb) d += Li1 * Li1;
        r0 += d; r1 += d; r2 += d;
    }

    #pragma unroll
    for (int o = 16; o > 0; o >>= 1) {
        r0 += __shfl_down_sync(0xffffffffu, r0, o);
        r1 += __shfl_down_sync(0xffffffffu, r1, o);
        r2 += __shfl_down_sync(0xffffffffu, r2, o);
    }
    int wid = tid >> 5, lane = tid & 31;
    if (lane == 0) { s_red[wid][0] = r0; s_red[wid][1] = r1; s_red[wid][2] = r2; }
    __syncthreads();
    if (tid == 0) {
        float s0 = 0.f, s1 = 0.f, s2 = 0.f;
        #pragma unroll
        for (int w = 0; w < 8; ++w) { s0 += s_red[w][0]; s1 += s_red[w][1]; s2 += s_red[w][2]; }
        g_bp[bid * 3 + 0] = s0; g_bp[bid * 3 + 1] = s1; g_bp[bid * 3 + 2] = s2;
    }
}

// ---------------- kernel 3: final combine ----------------
__global__ void combine_kernel(float* __restrict__ out) {
    __shared__ float sB[18];
    int t = threadIdx.x;           // 576 threads
    int cs = t >> 5, lane = t & 31;
    int cmb = cs / 3, s = cs - cmb * 3;

    int lo, n;
    if (cmb < 4) { lo = cmb * SYM_PER;                      n = SYM_PER;   }
    else         { lo = N_SYMITEMS + (cmb - 4) * CROSS_PER; n = CROSS_PER; }

    float acc = 0.f;
    for (int k = lane; k < n; k += 32)
        acc += g_bp[(lo + k) * 3 + s];
    #pragma unroll
    for (int o = 16; o > 0; o >>= 1)
        acc += __shfl_down_sync(0xffffffffu, acc, o);
    if (lane == 0) sB[cs] = acc;
    __syncthreads();

    if (t == 0) {
        const float w[3] = {1.0f, 0.25f, 0.16f};
        float loss = 0.f;
        #pragma unroll
        for (int b = 0; b < 2; ++b)
            #pragma unroll
            for (int s2 = 0; s2 < 3; ++s2)
                loss += w[s2] * (sB[b * 3 + s2]                  // pss
                                 - 2.0f * sB[(4 + b) * 3 + s2]   // pst
                                 + sB[(2 + b) * 3 + s2]);        // ptt
        out[0] = 0.5f * loss;   // mean over B=2
    }
}

// ncu's fixed capture lands on global launch index 3 (verified R1-R9).
// Fillers occupy indices 1 and 2 so index 3 = pair_kernel.
__global__ void filler1_kernel() {}
__global__ void filler2_kernel() {}

// ---------------- launch ----------------
extern "C" void kernel_launch(void* const* d_in, const int* in_sizes, int n_in,
                              void* d_out, int out_size) {
    const float* pred  = (const float*)d_in[0];
    const float* targ  = (const float*)d_in[1];
    const int*   faces = (const int*)d_in[2];
    float* out = (float*)d_out;

    mesh_kernel<<<(NMESH * F_ + 255) / 256, 256>>>(pred, targ, faces);   // idx 0
    filler1_kernel<<<1, 32>>>();                                         // idx 1
    filler2_kernel<<<1, 32>>>();                                         // idx 2
    pair_kernel<<<N_ITEMS, 256>>>();                                     // idx 3
    combine_kernel<<<1, 576>>>(out);                                     // idx 4
}

// round 11
// speedup vs baseline: 1.0683x; 1.0047x over previous
#include <cuda_runtime.h>
#include <cstdint>

// ---------------- problem constants ----------------
#define V_    5000
#define F_    6144
#define PB_   (F_/2)          // 3072 pair-blocks per mesh
#define NMESH 4               // pred0, pred1, targ0, targ1

#define K625      (-901.68440055560213f)   // -625*log2(e)
#define SI_       (1803.3688011112043f)    // -2*K625
#define SN2       5.7707801635558536f      // 4*log2(e)
#define SN_       2.4022448509f            // sqrt(SN2)

#define TILE_J   256
#define NTBJ     (F_ / TILE_J)             // 24 j-tiles of 256
#define ITILE    512
#define NTBI     (F_ / ITILE)              // 12 i-tiles of 512 (2 i per thread)

// sym combo items: (ti, jb) with jb >= 2*ti : sum_{ti=0..11} (24-2ti) = 156
#define SYM_PER    156
#define N_SYMITEMS (4 * SYM_PER)           // 624
#define CROSS_PER  (NTBI * NTBJ)           // 288
#define N_ITEMS    (N_SYMITEMS + 2 * CROSS_PER)   // 1200

typedef unsigned long long ull;

// ---------------- device scratch ----------------
__device__ float g_fd[NMESH * PB_ * 16];
__device__ float g_L [NMESH * F_];
__device__ float g_bp[N_ITEMS * 3];

// ---------------- f32x2 helpers ----------------
__device__ __forceinline__ ull f2fma(ull a, ull b, ull c) {
    ull d; asm("fma.rn.f32x2 %0, %1, %2, %3;" : "=l"(d) : "l"(a), "l"(b), "l"(c)); return d;
}
__device__ __forceinline__ ull f2mul(ull a, ull b) {
    ull d; asm("mul.rn.f32x2 %0, %1, %2;" : "=l"(d) : "l"(a), "l"(b)); return d;
}
__device__ __forceinline__ ull f2add(ull a, ull b) {
    ull d; asm("add.rn.f32x2 %0, %1, %2;" : "=l"(d) : "l"(a), "l"(b)); return d;
}
__device__ __forceinline__ ull splat2(float x) {
    ull d; asm("mov.b64 %0, {%1, %1};" : "=l"(d) : "f"(x)); return d;
}
__device__ __forceinline__ ull pack2(float lo, float hi) {
    ull d; asm("mov.b64 %0, {%1, %2};" : "=l"(d) : "f"(lo), "f"(hi)); return d;
}
__device__ __forceinline__ ull ex2x2(ull a) {
    ull r;
    asm("{\n\t"
        ".reg .f32 lo, hi;\n\t"
        "mov.b64 {lo, hi}, %1;\n\t"
        "ex2.approx.f32 lo, lo;\n\t"
        "ex2.approx.f32 hi, hi;\n\t"
        "mov.b64 %0, {lo, hi};\n\t"
        "}" : "=l"(r) : "l"(a));
    return r;
}
__device__ __forceinline__ float sum2(ull a) {
    float lo, hi;
    asm("mov.b64 {%0, %1}, %2;" : "=f"(lo), "=f"(hi) : "l"(a));
    return lo + hi;
}

// ---------------- kernel 1: per-face quantities ----------------
__global__ void mesh_kernel(const float* __restrict__ pred,
                            const float* __restrict__ targ,
                            const int*   __restrict__ faces) {
    int idx = blockIdx.x * blockDim.x + threadIdx.x;
    if (idx >= NMESH * F_) return;
    int m = idx / F_;
    int f = idx - m * F_;

    const float* Vb = (m < 2 ? pred : targ) + (m & 1) * (V_ * 3);

    int i0 = faces[3 * f + 0], i1 = faces[3 * f + 1], i2 = faces[3 * f + 2];
    float v0x = Vb[3*i0], v0y = Vb[3*i0+1], v0z = Vb[3*i0+2];
    float v1x = Vb[3*i1], v1y = Vb[3*i1+1], v1z = Vb[3*i1+2];
    float v2x = Vb[3*i2], v2y = Vb[3*i2+1], v2z = Vb[3*i2+2];

    const float third = 1.0f / 3.0f;
    float Cx = (v0x + v1x + v2x) * third;
    float Cy = (v0y + v1y + v2y) * third;
    float Cz = (v0z + v1z + v2z) * third;

    float e1x = v1x - v0x, e1y = v1y - v0y, e1z = v1z - v0z;
    float e2x = v2x - v0x, e2y = v2y - v0y, e2z = v2z - v0z;
    float Nx = 0.5f * (e1y * e2z - e1z * e2y);
    float Ny = 0.5f * (e1z * e2x - e1x * e2z);
    float Nz = 0.5f * (e1x * e2y - e1y * e2x);

    float n2 = Nx*Nx + Ny*Ny + Nz*Nz + 1e-24f;
    float L  = sqrtf(n2);
    float s  = SN_ / L;

    float A  = K625 * (Cx*Cx + Cy*Cy + Cz*Cz);
    float G  = log2f(L) - SN2;

    int base = m * (PB_ * 16) + (f >> 1) * 16 + (f & 1);
    g_fd[base + 0]  = Cx;
    g_fd[base + 2]  = Cy;
    g_fd[base + 4]  = Cz;
    g_fd[base + 6]  = A;
    g_fd[base + 8]  = Nx * s;
    g_fd[base + 10] = Ny * s;
    g_fd[base + 12] = Nz * s;
    g_fd[base + 14] = G;
    g_L[m * F_ + f] = L;
}

// ---------------- kernel 2: pairwise varifold products ----------------
// grid = 1200 equal work items. block = 256 threads; each thread owns TWO
// i-faces (i, i+256) of a 512-i tile; one 256-j tile staged in 8 KB smem.

struct IFace { ull RX, RY, RZ, AiD, NX, NY, NZ; };
struct Acc3  { ull a0, a1, a2; };

template <bool DIAG>
__device__ __forceinline__ void tile_loop2(const ulonglong2* __restrict__ s_tile,
                                           const IFace& I0, const IFace& I1,
                                           int jmi0, int jmi1,
                                           Acc3& A0, Acc3& A1) {
    ull a00 = A0.a0, a01 = A0.a1, a02 = A0.a2;
    ull a10 = A1.a0, a11 = A1.a1, a12 = A1.a2;
    #pragma unroll 8
    for (int p = 0; p < TILE_J / 2; ++p) {
        ulonglong2 q0 = s_tile[p * 4 + 0];   // Cx | Cy
        ulonglong2 q1 = s_tile[p * 4 + 1];   // Cz | A
        ulonglong2 q2 = s_tile[p * 4 + 2];   // Nx | Ny
        ulonglong2 q3 = s_tile[p * 4 + 3];   // Nz | G

        // -------- chain 0: exponents --------
        ull p0a = f2fma(I0.RX, q0.x, I0.AiD);
        ull p0b = f2fma(I0.RY, q0.y, q1.y);
        p0a = f2fma(I0.RZ, q1.x, p0a);
        ull arg0 = f2add(p0a, p0b);
        ull narg0 = f2fma(I0.NX, q2.x, q3.y);
        narg0 = f2fma(I0.NY, q2.y, narg0);
        narg0 = f2fma(I0.NZ, q3.x, narg0);

        // -------- chain 1: exponents --------
        ull p1a = f2fma(I1.RX, q0.x, I1.AiD);
        ull p1b = f2fma(I1.RY, q0.y, q1.y);
        p1a = f2fma(I1.RZ, q1.x, p1a);
        ull arg1 = f2add(p1a, p1b);
        ull narg1 = f2fma(I1.NX, q2.x, q3.y);
        narg1 = f2fma(I1.NY, q2.y, narg1);
        narg1 = f2fma(I1.NZ, q3.x, narg1);

        ull y0  = ex2x2(arg0);
        ull en0 = ex2x2(narg0);
        ull y1  = ex2x2(arg1);
        ull en1 = ex2x2(narg1);

        if (DIAG) {
            float w0lo = (2 * p + jmi0     > 0) ? 2.0f : 0.0f;
            float w0hi = (2 * p + jmi0 + 1 > 0) ? 2.0f : 0.0f;
            en0 = f2mul(en0, pack2(w0lo, w0hi));
            float w1lo = (2 * p + jmi1     > 0) ? 2.0f : 0.0f;
            float w1hi = (2 * p + jmi1 + 1 > 0) ? 2.0f : 0.0f;
            en1 = f2mul(en1, pack2(w1lo, w1hi));
        }

        // -------- powers + accum, chain 0 (depth-5: y9 || y16) --------
        {
            ull y2  = f2mul(y0, y0);
            ull y4  = f2mul(y2, y2);
            ull y8  = f2mul(y4, y4);
            ull y9  = f2mul(y8, y0);
            ull y16 = f2mul(y8, y8);
            ull y25 = f2mul(y16, y9);
            a00 = f2fma(en0, y4,  a00);   // sigma=0.02  (2500 =4*625)
            a01 = f2fma(en0, y16, a01);   // sigma=0.01  (10000=16*625)
            a02 = f2fma(en0, y25, a02);   // sigma=0.008 (15625=25*625)
        }
        // -------- powers + accum, chain 1 --------
        {
            ull y2  = f2mul(y1, y1);
            ull y4  = f2mul(y2, y2);
            ull y8  = f2mul(y4, y4);
            ull y9  = f2mul(y8, y1);
            ull y16 = f2mul(y8, y8);
            ull y25 = f2mul(y16, y9);
            a10 = f2fma(en1, y4,  a10);
            a11 = f2fma(en1, y16, a11);
            a12 = f2fma(en1, y25, a12);
        }
    }
    A0.a0 = a00; A0.a1 = a01; A0.a2 = a02;
    A1.a0 = a10; A1.a1 = a11; A1.a2 = a12;
}

__device__ __forceinline__ void load_iface(int m, int i, IFace& I) {
    int b = m * (PB_ * 16) + (i >> 1) * 16 + (i & 1);
    I.RX  = splat2(SI_ * g_fd[b + 0]);
    I.RY  = splat2(SI_ * g_fd[b + 2]);
    I.RZ  = splat2(SI_ * g_fd[b + 4]);
    I.AiD = splat2(g_fd[b + 6]);
    I.NX  = splat2(g_fd[b + 8]);
    I.NY  = splat2(g_fd[b + 10]);
    I.NZ  = splat2(g_fd[b + 12]);
}

__global__ __launch_bounds__(256, 3)
void pair_kernel() {
    __shared__ ulonglong2 s_tile[(TILE_J / 2) * 4];   // 8 KB
    __shared__ float s_red[8][3];

    int bid = blockIdx.x;
    int tid = threadIdx.x;

    // ---- decode work item ----
    int mi, mj, ti, jb;
    bool diag = false;
    float mult = 1.0f;
    if (bid < N_SYMITEMS) {
        int c = bid / SYM_PER;
        int k = bid - c * SYM_PER;
        int row = 0;
        while (k >= NTBJ - 2 * row) { k -= NTBJ - 2 * row; ++row; }
        ti = row; jb = 2 * row + k;
        mi = mj = c;
        diag = ((jb >> 1) == ti);
        mult = diag ? 1.0f : 2.0f;
    } else {
        int k = bid - N_SYMITEMS;
        int c = k / CROSS_PER; k -= c * CROSS_PER;
        ti = k / NTBJ; jb = k - ti * NTBJ;
        mi = c; mj = c + 2;
    }

    int i0 = ti * ITILE + tid;
    int i1 = i0 + 256;

    IFace I0, I1;
    load_iface(mi, i0, I0);
    load_iface(mi, i1, I1);
    float Li0 = g_L[mi * F_ + i0];
    float Li1 = g_L[mi * F_ + i1];

    // stage the 256-face j-tile (128 pair-blocks * 64 B = 8 KB)
    {
        float4* dst = (float4*)s_tile;
        const float4* src = (const float4*)(g_fd + (size_t)mj * (PB_ * 16))
                          + (size_t)jb * (TILE_J / 2) * 4;
        #pragma unroll
        for (int k = 0; k < (TILE_J / 2) * 4 / 256; ++k)
            dst[tid + k * 256] = src[tid + k * 256];
    }
    __syncthreads();

    Acc3 A0, A1;
    A0.a0 = splat2(0.f); A0.a1 = splat2(0.f); A0.a2 = splat2(0.f);
    A1.a0 = splat2(0.f); A1.a1 = splat2(0.f); A1.a2 = splat2(0.f);

    if (diag)
        tile_loop2<true >(s_tile, I0, I1, jb * TILE_J - i0, jb * TILE_J - i1, A0, A1);
    else
        tile_loop2<false>(s_tile, I0, I1, 0, 0, A0, A1);

    float r0 = mult * (Li0 * sum2(A0.a0) + Li1 * sum2(A1.a0));
    float r1 = mult * (Li0 * sum2(A0.a1) + Li1 * sum2(A1.a1));
    float r2 = mult * (Li0 * sum2(A0.a2) + Li1 * sum2(A1.a2));
    if (diag) {                              // K(i,i) = 1 exactly
        float d = 0.f;
        if ((i0 >> 8) == jb) d += Li0 * Li0;
        if ((i1 >> 8) == jb) d += Li1 * Li1;
        r0 += d; r1 += d; r2 += d;
    }

    #pragma unroll
    for (int o = 16; o > 0; o >>= 1) {
        r0 += __shfl_down_sync(0xffffffffu, r0, o);
        r1 += __shfl_down_sync(0xffffffffu, r1, o);
        r2 += __shfl_down_sync(0xffffffffu, r2, o);
    }
    int wid = tid >> 5, lane = tid & 31;
    if (lane == 0) { s_red[wid][0] = r0; s_red[wid][1] = r1; s_red[wid][2] = r2; }
    __syncthreads();
    if (tid == 0) {
        float s0 = 0.f, s1 = 0.f, s2 = 0.f;
        #pragma unroll
        for (int w = 0; w < 8; ++w) { s0 += s_red[w][0]; s1 += s_red[w][1]; s2 += s_red[w][2]; }
        g_bp[bid * 3 + 0] = s0; g_bp[bid * 3 + 1] = s1; g_bp[bid * 3 + 2] = s2;
    }
}

// ---------------- kernel 3: final combine ----------------
__global__ void combine_kernel(float* __restrict__ out) {
    __shared__ float sB[18];
    int t = threadIdx.x;           // 576 threads
    int cs = t >> 5, lane = t & 31;
    int cmb = cs / 3, s = cs - cmb * 3;

    int lo, n;
    if (cmb < 4) { lo = cmb * SYM_PER;                      n = SYM_PER;   }
    else         { lo = N_SYMITEMS + (cmb - 4) * CROSS_PER; n = CROSS_PER; }

    float acc = 0.f;
    for (int k = lane; k < n; k += 32)
        acc += g_bp[(lo + k) * 3 + s];
    #pragma unroll
    for (int o = 16; o > 0; o >>= 1)
        acc += __shfl_down_sync(0xffffffffu, acc, o);
    if (lane == 0) sB[cs] = acc;
    __syncthreads();

    if (t == 0) {
        const float w[3] = {1.0f, 0.25f, 0.16f};
        float loss = 0.f;
        #pragma unroll
        for (int b = 0; b < 2; ++b)
            #pragma unroll
            for (int s2 = 0; s2 < 3; ++s2)
                loss += w[s2] * (sB[b * 3 + s2]                  // pss
                                 - 2.0f * sB[(4 + b) * 3 + s2]   // pst
                                 + sB[(2 + b) * 3 + s2]);        // ptt
        out[0] = 0.5f * loss;   // mean over B=2
    }
}

// ---------------- launch ----------------
// Fillers removed: profiling established the kernel is FMA-roof-bound; the
// two empty launches cost ~4-6 us of pure graph overhead.
extern "C" void kernel_launch(void* const* d_in, const int* in_sizes, int n_in,
                              void* d_out, int out_size) {
    const float* pred  = (const float*)d_in[0];
    const float* targ  = (const float*)d_in[1];
    const int*   faces = (const int*)d_in[2];
    float* out = (float*)d_out;

    mesh_kernel<<<(NMESH * F_ + 255) / 256, 256>>>(pred, targ, faces);
    pair_kernel<<<N_ITEMS, 256>>>();
    combine_kernel<<<1, 576>>>(out);
}